// round 9
// baseline (speedup 1.0000x reference)
#include <cuda_runtime.h>

// Online Normalization forward, group-pipelined persistent kernel (v9).
// x: [B=32, H=64, W=64, C=256] channels-last, fp32.
//
// 128 CTAs x 1024 threads (1/SM, co-resident -> grid barrier safe).
// Batches split into 4 groups of 8 (32 MB each). Stage g: stream stats of
// group g INTERLEAVED with normalize of group g-1 (read one stage ago ->
// guaranteed L2-resident). DRAM traffic = exact floor (134 MB read + 134 MB
// write). All streaming loops static (16 iters). EMA state carried in
// registers (threads 0..255); mu/rs double-buffered in smem.

#define AFWD 0.999f
#define EPS  1e-5f

constexpr int Bn   = 32;
constexpr int HW   = 64 * 64;      // 4096 rows per batch
constexpr int Cc   = 256;
constexpr int C4   = Cc / 4;       // 64
constexpr int GRP  = 8;            // batches per group
constexpr int NG   = Bn / GRP;     // 4 groups
constexpr int NCTA = 128;
constexpr int TPB  = 1024;
constexpr int RG   = TPB / C4;     // 16 row groups
constexpr int CH   = 256;          // rows per CTA per stage (8*4096/128)
constexpr int IT   = CH / RG;      // 16 iterations

__device__ float g_ps[Bn * 16 * Cc];   // per-(batch,chunk) partial sums
__device__ float g_pq[Bn * 16 * Cc];
__device__ unsigned long long g_bar;   // monotonic across graph replays

// smem layout (floats)
constexpr int SM_RED_S = 0;        // 4096
constexpr int SM_RED_Q = 4096;     // 4096
constexpr int SM_ST_S  = 8192;     // 2048
constexpr int SM_ST_Q  = 10240;    // 2048
constexpr int SM_MU0   = 12288;    // 2048  (mu for even-group buffer)
constexpr int SM_RS0   = 14336;    // 2048
constexpr int SM_MU1   = 16384;    // 2048  (odd-group buffer)
constexpr int SM_RS1   = 18432;    // 2048
constexpr int SMEM_FLOATS = 20480; // 80 KB

__device__ __forceinline__ void grid_barrier() {
    __syncthreads();
    if (threadIdx.x == 0) {
        __threadfence();
        unsigned long long t = atomicAdd(&g_bar, 1ULL) + 1ULL;
        unsigned long long target = ((t + NCTA - 1ULL) / NCTA) * NCTA;
        while (*((volatile unsigned long long*)&g_bar) < target) { }
        __threadfence();
    }
    __syncthreads();
}

__global__ __launch_bounds__(TPB, 1)
void onorm_pipe(const float4* __restrict__ x4,
                float4* __restrict__ o4,
                const float* __restrict__ mu0,
                const float* __restrict__ var0) {
    extern __shared__ float sm[];
    const int tid = threadIdx.x;
    const int j   = blockIdx.x;
    const int c4  = tid & 63;       // float4 channel index
    const int rg  = tid >> 6;       // 0..15 row group
    const int bg  = j >> 4;         // batch-in-group handled by this CTA
    const int ch  = j & 15;         // 256-row chunk within that batch

    // EMA state carried in registers by threads 0..255
    float mu = 0.f, var = 1.f;
    if (tid < Cc) { mu = mu0[tid]; var = var0[tid]; }

    for (int g = 0; g <= NG; g++) {
        const bool do_stats = (g < NG);
        const bool do_norm  = (g > 0);

        // ---- streaming: stats(group g) interleaved with norm(group g-1) ----
        float4 a = {0.f,0.f,0.f,0.f}, q = {0.f,0.f,0.f,0.f};
        const size_t sb = ((size_t)((g % NG) * GRP + bg) * HW
                           + (size_t)ch * CH + rg) * C4 + c4;   // stats idx
        const size_t nb = ((size_t)(((g - 1) & 3) * GRP + bg) * HW
                           + (size_t)ch * CH + rg) * C4 + c4;   // norm idx

        if (do_stats && do_norm) {
            const float* mub = sm + (((g - 1) & 1) ? SM_MU1 : SM_MU0);
            const float* rsb = sm + (((g - 1) & 1) ? SM_RS1 : SM_RS0);
            const float4 m = ((const float4*)mub)[bg * 64 + c4];
            const float4 r = ((const float4*)rsb)[bg * 64 + c4];
            #pragma unroll
            for (int i = 0; i < IT; i++) {
                float4 vs = x4[sb + (size_t)i * RG * C4];
                float4 vn = __ldcs(&x4[nb + (size_t)i * RG * C4]);
                a.x += vs.x; a.y += vs.y; a.z += vs.z; a.w += vs.w;
                q.x = fmaf(vs.x, vs.x, q.x); q.y = fmaf(vs.y, vs.y, q.y);
                q.z = fmaf(vs.z, vs.z, q.z); q.w = fmaf(vs.w, vs.w, q.w);
                float4 w;
                w.x = (vn.x - m.x) * r.x;
                w.y = (vn.y - m.y) * r.y;
                w.z = (vn.z - m.z) * r.z;
                w.w = (vn.w - m.w) * r.w;
                __stcs(&o4[nb + (size_t)i * RG * C4], w);
            }
        } else if (do_stats) {              // stage 0: stats only
            #pragma unroll
            for (int i = 0; i < IT; i++) {
                float4 vs = x4[sb + (size_t)i * RG * C4];
                a.x += vs.x; a.y += vs.y; a.z += vs.z; a.w += vs.w;
                q.x = fmaf(vs.x, vs.x, q.x); q.y = fmaf(vs.y, vs.y, q.y);
                q.z = fmaf(vs.z, vs.z, q.z); q.w = fmaf(vs.w, vs.w, q.w);
            }
        } else {                            // stage NG: norm only
            const float* mub = sm + (((g - 1) & 1) ? SM_MU1 : SM_MU0);
            const float* rsb = sm + (((g - 1) & 1) ? SM_RS1 : SM_RS0);
            const float4 m = ((const float4*)mub)[bg * 64 + c4];
            const float4 r = ((const float4*)rsb)[bg * 64 + c4];
            #pragma unroll
            for (int i = 0; i < IT; i++) {
                float4 vn = __ldcs(&x4[nb + (size_t)i * RG * C4]);
                float4 w;
                w.x = (vn.x - m.x) * r.x;
                w.y = (vn.y - m.y) * r.y;
                w.z = (vn.z - m.z) * r.z;
                w.w = (vn.w - m.w) * r.w;
                __stcs(&o4[nb + (size_t)i * RG * C4], w);
            }
        }

        if (!do_stats) break;               // stage NG has no reduce/scan

        // ---- smem reduce of this CTA's chunk partials -> gmem ----
        ((float4*)(sm + SM_RED_S))[rg * 64 + c4] = a;
        ((float4*)(sm + SM_RED_Q))[rg * 64 + c4] = q;
        __syncthreads();
        if (tid < 64) {
            float4 sa = {0.f,0.f,0.f,0.f}, sq = {0.f,0.f,0.f,0.f};
            #pragma unroll
            for (int k = 0; k < RG; k++) {
                float4 va = ((float4*)(sm + SM_RED_S))[k * 64 + tid];
                float4 vq = ((float4*)(sm + SM_RED_Q))[k * 64 + tid];
                sa.x += va.x; sa.y += va.y; sa.z += va.z; sa.w += va.w;
                sq.x += vq.x; sq.y += vq.y; sq.z += vq.z; sq.w += vq.w;
            }
            const int tile = (g * GRP + bg) * 16 + ch;
            ((float4*)g_ps)[tile * 64 + tid] = sa;
            ((float4*)g_pq)[tile * 64 + tid] = sq;
        }

        grid_barrier();

        // ---- fold group g's 16 chunk-partials per batch into smem ----
        for (int i = tid; i < GRP * Cc; i += TPB) {
            const int b = i >> 8, c = i & 255;
            const int base = ((g * GRP + b) * 16) * Cc + c;
            float ss = 0.f, qq = 0.f;
            #pragma unroll
            for (int k = 0; k < 16; k++) {
                ss += g_ps[base + k * Cc];
                qq += g_pq[base + k * Cc];
            }
            sm[SM_ST_S + i] = ss;
            sm[SM_ST_Q + i] = qq;
        }
        __syncthreads();

        // ---- 8-step EMA scan into buffer g&1 (state stays in registers) ----
        if (tid < Cc) {
            float* mub = sm + ((g & 1) ? SM_MU1 : SM_MU0);
            float* rsb = sm + ((g & 1) ? SM_RS1 : SM_RS0);
            const float inv = 1.0f / (float)HW;
            #pragma unroll
            for (int b = 0; b < GRP; b++) {
                mub[b * Cc + tid] = mu;
                rsb[b * Cc + tid] = rsqrtf(var + EPS);
                const float mean = sm[SM_ST_S + b * Cc + tid] * inv;
                const float vart = fmaf(-mean, mean, sm[SM_ST_Q + b * Cc + tid] * inv);
                const float d    = mean - mu;
                var = AFWD * var + (1.0f - AFWD) * vart
                    + AFWD * (1.0f - AFWD) * d * d;
                mu  = fmaf(1.0f - AFWD, d, mu);
            }
        }
        __syncthreads();
    }
}

extern "C" void kernel_launch(void* const* d_in, const int* in_sizes, int n_in,
                              void* d_out, int out_size) {
    const float* x    = (const float*)d_in[0];
    const float* mu0  = (const float*)d_in[1];
    const float* var0 = (const float*)d_in[2];
    float* out = (float*)d_out;

    static bool attr_set = false;
    if (!attr_set) {
        cudaFuncSetAttribute(onorm_pipe,
                             cudaFuncAttributeMaxDynamicSharedMemorySize,
                             SMEM_FLOATS * sizeof(float));
        attr_set = true;
    }

    onorm_pipe<<<NCTA, TPB, SMEM_FLOATS * sizeof(float)>>>(
        (const float4*)x, (float4*)out, mu0, var0);
}

// round 10
// speedup vs baseline: 1.0971x; 1.0971x over previous
#include <cuda_runtime.h>

// Online Normalization forward, fused persistent kernel (v10 = v4 + stolen pass 3).
// x: [B=32, H=64, W=64, C=256] channels-last, fp32.
//
// 128 CTAs x 1024 threads (1/SM, co-resident -> grid barrier safe).
// Pass 1 (static, v4): CTA (t*4+q) streams quarter q of batch t (1 MB),
// register accumulation, one smem reduce -> gmem partials. One grid barrier.
// All CTAs fold partials + run the full 32-step EMA scan into smem mu/rs.
// Pass 3: work-stealing over 512 tiles of 256 rows (reverse order), ticket
// counter is monotonic across graph replays (exactly 640 grabs per launch:
// 512 successful + 128 terminal). Streaming stores.

#define AFWD 0.999f
#define EPS  1e-5f

constexpr int Bn    = 32;
constexpr int HW    = 64 * 64;       // 4096 rows per batch
constexpr int Cc    = 256;
constexpr int C4    = Cc / 4;        // 64
constexpr int NCTA  = 128;
constexpr int TPB   = 1024;
constexpr int ROWS  = HW / 4;        // 1024 rows per CTA in pass 1
constexpr int ITER  = ROWS / 16;     // 64 rows per thread
constexpr int TROWS = 256;           // tile rows in pass 3
constexpr int NTILE = Bn * HW / TROWS;          // 512
constexpr unsigned long long EPOCH = NTILE + NCTA;   // 640 grabs per launch

__device__ float g_ps[NCTA * Cc];    // per-chunk partial sums
__device__ float g_pq[NCTA * Cc];
__device__ unsigned long long g_bar;   // monotonic across replays
__device__ unsigned long long g_tick;  // monotonic ticket counter

// Dynamic smem (floats):
//   [0 : 16384)   union: pass1 reduce (red_s 0:4096, red_q 4096:8192)
//                         staging (st_s 0:8192, st_q 8192:16384)
//   [16384:24576) sm_mu [32 x 256]
//   [24576:32768) sm_rs [32 x 256]
constexpr int SMEM_FLOATS = 32768;   // 128 KB

__device__ __forceinline__ void grid_barrier() {
    __syncthreads();
    if (threadIdx.x == 0) {
        __threadfence();
        unsigned long long t = atomicAdd(&g_bar, 1ULL) + 1ULL;
        unsigned long long target = ((t + NCTA - 1ULL) / NCTA) * NCTA;
        while (*((volatile unsigned long long*)&g_bar) < target) { }
        __threadfence();
    }
    __syncthreads();
}

__global__ __launch_bounds__(TPB, 1)
void onorm_fused(const float4* __restrict__ x4,
                 float4* __restrict__ o4,
                 const float* __restrict__ mu0,
                 const float* __restrict__ var0) {
    extern __shared__ float sm[];
    float* red_s = sm;                 // 4096 floats
    float* red_q = sm + 4096;          // 4096 floats
    float* st_s  = sm;                 // 8192 floats (after barrier)
    float* st_q  = sm + 8192;          // 8192 floats
    float* sm_mu = sm + 16384;         // 8192 floats
    float* sm_rs = sm + 24576;         // 8192 floats
    __shared__ unsigned long long s_tk;

    const int tid = threadIdx.x;
    const int cta = blockIdx.x;
    const int c4  = tid & 63;          // float4 channel index
    const int rg  = tid >> 6;          // 0..15 row group
    const int t   = cta >> 2;          // batch owned in pass 1
    const int qq  = cta & 3;           // quarter of the batch

    const size_t base = ((size_t)t * HW + (size_t)qq * ROWS + rg) * C4;
    const float4* p = x4 + base + c4;

    // ---------------- Pass 1: sync-free streaming accumulation ----------------
    float4 a = {0.f,0.f,0.f,0.f}, q = {0.f,0.f,0.f,0.f};
    #pragma unroll 8
    for (int i = 0; i < ITER; i++) {
        float4 v = p[(size_t)i * 16 * C4];
        a.x += v.x; a.y += v.y; a.z += v.z; a.w += v.w;
        q.x = fmaf(v.x, v.x, q.x); q.y = fmaf(v.y, v.y, q.y);
        q.z = fmaf(v.z, v.z, q.z); q.w = fmaf(v.w, v.w, q.w);
    }
    ((float4*)red_s)[rg * 64 + c4] = a;
    ((float4*)red_q)[rg * 64 + c4] = q;
    __syncthreads();
    if (tid < 64) {
        float4 sa = {0.f,0.f,0.f,0.f}, sq = {0.f,0.f,0.f,0.f};
        #pragma unroll
        for (int j = 0; j < 16; j++) {
            float4 va = ((float4*)red_s)[j * 64 + tid];
            float4 vq = ((float4*)red_q)[j * 64 + tid];
            sa.x += va.x; sa.y += va.y; sa.z += va.z; sa.w += va.w;
            sq.x += vq.x; sq.y += vq.y; sq.z += vq.z; sq.w += vq.w;
        }
        ((float4*)g_ps)[cta * 64 + tid] = sa;
        ((float4*)g_pq)[cta * 64 + tid] = sq;
    }

    grid_barrier();   // partials visible; red area retired for staging reuse

    // ------- Staging: fold 4 quarter-partials per (batch, channel) ------------
    for (int i = tid; i < Bn * Cc; i += TPB) {
        const int b = ((i >> 8) << 10) + (i & 255);   // (tt*4)*Cc + c
        st_s[i] = g_ps[b] + g_ps[b + 256] + g_ps[b + 512] + g_ps[b + 768];
        st_q[i] = g_pq[b] + g_pq[b + 256] + g_pq[b + 512] + g_pq[b + 768];
    }
    __syncthreads();

    // ------------- Scan: full 32-step EMA recurrence into smem ----------------
    if (tid < Cc) {
        const int c = tid;
        float mu  = mu0[c];
        float var = var0[c];
        const float inv = 1.0f / (float)HW;
        #pragma unroll
        for (int tt = 0; tt < Bn; tt++) {
            sm_mu[tt * Cc + c] = mu;
            sm_rs[tt * Cc + c] = rsqrtf(var + EPS);
            const float mean = st_s[tt * Cc + c] * inv;
            const float vart = fmaf(-mean, mean, st_q[tt * Cc + c] * inv);
            const float d    = mean - mu;
            var = AFWD * var + (1.0f - AFWD) * vart
                + AFWD * (1.0f - AFWD) * d * d;
            mu  = fmaf(1.0f - AFWD, d, mu);
        }
    }
    __syncthreads();

    // ---------------- Pass 3: work-stealing normalize ----------------
    // Ticket counter is monotonic; per launch exactly NTILE successful grabs
    // plus one terminal grab per CTA => EPOCH consumed. Epoch base recovered
    // from the first grab. Tiles processed newest-first (reverse) for L2 hits.
    if (tid == 0) s_tk = atomicAdd(&g_tick, 1ULL);
    __syncthreads();
    unsigned long long tk = s_tk;
    const unsigned long long ebase = (tk / EPOCH) * EPOCH;
    const unsigned long long eend  = ebase + (unsigned long long)NTILE;

    while (tk < eend) {
        const int tile = NTILE - 1 - (int)(tk - ebase);
        const int r0   = tile * TROWS;
        const int b    = r0 >> 12;                 // batch of this tile
        const float4 m = ((const float4*)sm_mu)[b * 64 + c4];
        const float4 r = ((const float4*)sm_rs)[b * 64 + c4];
        const size_t tb = ((size_t)r0 + rg) * C4 + c4;
        #pragma unroll
        for (int i = 0; i < TROWS / 16; i++) {
            float4 v = x4[tb + (size_t)i * 16 * C4];
            float4 w;
            w.x = (v.x - m.x) * r.x;
            w.y = (v.y - m.y) * r.y;
            w.z = (v.z - m.z) * r.z;
            w.w = (v.w - m.w) * r.w;
            __stcs(&o4[tb + (size_t)i * 16 * C4], w);
        }
        __syncthreads();                    // all threads done with s_tk
        if (tid == 0) s_tk = atomicAdd(&g_tick, 1ULL);
        __syncthreads();
        tk = s_tk;
    }
}

extern "C" void kernel_launch(void* const* d_in, const int* in_sizes, int n_in,
                              void* d_out, int out_size) {
    const float* x    = (const float*)d_in[0];
    const float* mu0  = (const float*)d_in[1];
    const float* var0 = (const float*)d_in[2];
    float* out = (float*)d_out;

    static bool attr_set = false;
    if (!attr_set) {
        cudaFuncSetAttribute(onorm_fused,
                             cudaFuncAttributeMaxDynamicSharedMemorySize,
                             SMEM_FLOATS * sizeof(float));
        attr_set = true;
    }

    onorm_fused<<<NCTA, TPB, SMEM_FLOATS * sizeof(float)>>>(
        (const float4*)x, (float4*)out, mu0, var0);
}

// round 11
// speedup vs baseline: 1.1431x; 1.0419x over previous
#include <cuda_runtime.h>

// Online Normalization forward, fused persistent kernel (v11 = v4 in 2 stages).
// x: [B=32, H=64, W=64, C=256] channels-last, fp32.
//
// 128 CTAs x 1024 threads (1/SM, co-resident -> grid barrier safe).
// 2 super-stages of 16 batches (67 MB each; fits L2 with margin).
// Per stage: stats-stream 512 rows/CTA (static loop) -> grid barrier ->
// fold + EMA scan (state carried in registers of tid<256) -> normalize the
// same 512 rows in reverse order (plain loads: L1 + guaranteed-L2 hits),
// streaming stores. Partials double-buffered by stage parity.

#define AFWD 0.999f
#define EPS  1e-5f

constexpr int Bn   = 32;
constexpr int HW   = 64 * 64;      // 4096 rows per batch
constexpr int Cc   = 256;
constexpr int C4   = Cc / 4;       // 64
constexpr int NCTA = 128;
constexpr int TPB  = 1024;
constexpr int NSTG = 2;
constexpr int GB   = Bn / NSTG;    // 16 batches per stage
constexpr int CPB  = NCTA / GB;    // 8 CTAs per batch
constexpr int ROWS = HW / CPB;     // 512 rows per CTA per stage
constexpr int RG   = TPB / C4;     // 16 row groups
constexpr int ITER = ROWS / RG;    // 32 rows per thread per stage

__device__ float g_ps[NSTG][NCTA * Cc];   // per-chunk partials, stage-buffered
__device__ float g_pq[NSTG][NCTA * Cc];
__device__ unsigned long long g_bar;      // monotonic across graph replays

// Dynamic smem (floats):
//   [0 : 8192)    union: pass1 reduce (red_s 0:4096, red_q 4096:8192)
//                        staging (st_s 0:4096, st_q 4096:8192)
//   [8192 : 12288)  sm_mu [16 x 256]
//   [12288: 16384)  sm_rs [16 x 256]
constexpr int SMEM_FLOATS = 16384;        // 64 KB -> L1D ~162 KB

__device__ __forceinline__ void grid_barrier() {
    __syncthreads();
    if (threadIdx.x == 0) {
        __threadfence();
        unsigned long long t = atomicAdd(&g_bar, 1ULL) + 1ULL;
        unsigned long long target = ((t + NCTA - 1ULL) / NCTA) * NCTA;
        while (*((volatile unsigned long long*)&g_bar) < target) { }
        __threadfence();
    }
    __syncthreads();
}

__global__ __launch_bounds__(TPB, 1)
void onorm_fused(const float4* __restrict__ x4,
                 float4* __restrict__ o4,
                 const float* __restrict__ mu0,
                 const float* __restrict__ var0) {
    extern __shared__ float sm[];
    float* red_s = sm;                 // 4096 floats
    float* red_q = sm + 4096;          // 4096 floats
    float* st_s  = sm;                 // 4096 floats (after barrier)
    float* st_q  = sm + 4096;          // 4096 floats
    float* sm_mu = sm + 8192;          // 4096 floats
    float* sm_rs = sm + 12288;         // 4096 floats

    const int tid = threadIdx.x;
    const int cta = blockIdx.x;
    const int c4  = tid & 63;          // float4 channel index
    const int rg  = tid >> 6;          // 0..15 row group
    const int bl  = cta >> 3;          // local batch index (0..15)
    const int s   = cta & 7;           // chunk within the batch

    // EMA state carried across stages in registers of threads 0..255
    float mu = 0.f, var = 1.f;
    if (tid < Cc) { mu = mu0[tid]; var = var0[tid]; }

    #pragma unroll
    for (int g = 0; g < NSTG; g++) {
        const int t = g * GB + bl;     // global batch this CTA handles
        const size_t base = ((size_t)t * HW + (size_t)s * ROWS + rg) * C4 + c4;
        const float4* p = x4 + base;

        // ---------- stats: pure read stream, static loop ----------
        float4 a = {0.f,0.f,0.f,0.f}, q = {0.f,0.f,0.f,0.f};
        #pragma unroll 8
        for (int i = 0; i < ITER; i++) {
            float4 v = p[(size_t)i * RG * C4];
            a.x += v.x; a.y += v.y; a.z += v.z; a.w += v.w;
            q.x = fmaf(v.x, v.x, q.x); q.y = fmaf(v.y, v.y, q.y);
            q.z = fmaf(v.z, v.z, q.z); q.w = fmaf(v.w, v.w, q.w);
        }
        ((float4*)red_s)[rg * 64 + c4] = a;
        ((float4*)red_q)[rg * 64 + c4] = q;
        __syncthreads();
        if (tid < 64) {
            float4 sa = {0.f,0.f,0.f,0.f}, sq = {0.f,0.f,0.f,0.f};
            #pragma unroll
            for (int j = 0; j < RG; j++) {
                float4 va = ((float4*)red_s)[j * 64 + tid];
                float4 vq = ((float4*)red_q)[j * 64 + tid];
                sa.x += va.x; sa.y += va.y; sa.z += va.z; sa.w += va.w;
                sq.x += vq.x; sq.y += vq.y; sq.z += vq.z; sq.w += vq.w;
            }
            ((float4*)g_ps[g])[cta * 64 + tid] = sa;
            ((float4*)g_pq[g])[cta * 64 + tid] = sq;
        }

        grid_barrier();   // partials visible; red area retired for staging

        // ---------- fold 8 chunk-partials per batch into smem ----------
        // i encodes (bb, c): bb = i>>8 in [0,16), c = i&255
        for (int i = tid; i < GB * Cc; i += TPB) {
            const int b = ((i >> 8) << 3) * Cc + (i & 255);   // (bb*8)*Cc + c
            float ss = 0.f, qq = 0.f;
            #pragma unroll
            for (int k = 0; k < CPB; k++) {
                ss += g_ps[g][b + k * Cc];
                qq += g_pq[g][b + k * Cc];
            }
            st_s[i] = ss;
            st_q[i] = qq;
        }
        __syncthreads();

        // ---------- 16-step EMA scan (register state) into smem mu/rs ----------
        if (tid < Cc) {
            const float inv = 1.0f / (float)HW;
            #pragma unroll
            for (int b = 0; b < GB; b++) {
                sm_mu[b * Cc + tid] = mu;
                sm_rs[b * Cc + tid] = rsqrtf(var + EPS);
                const float mean = st_s[b * Cc + tid] * inv;
                const float vart = fmaf(-mean, mean, st_q[b * Cc + tid] * inv);
                const float d    = mean - mu;
                var = AFWD * var + (1.0f - AFWD) * vart
                    + AFWD * (1.0f - AFWD) * d * d;
                mu  = fmaf(1.0f - AFWD, d, mu);
            }
        }
        __syncthreads();

        // ---------- normalize: pure write stream, reverse order ----------
        // Plain loads: tail of chunk still in L1 (~160 KB) + all in L2 (67 MB
        // stage set << 126 MB L2). Streaming stores keep out of L2.
        const float4 m = ((const float4*)sm_mu)[bl * 64 + c4];
        const float4 r = ((const float4*)sm_rs)[bl * 64 + c4];
        float4* o = o4 + base;
        #pragma unroll 8
        for (int i = ITER - 1; i >= 0; i--) {
            float4 v = p[(size_t)i * RG * C4];
            float4 w;
            w.x = (v.x - m.x) * r.x;
            w.y = (v.y - m.y) * r.y;
            w.z = (v.z - m.z) * r.z;
            w.w = (v.w - m.w) * r.w;
            __stcs(&o[(size_t)i * RG * C4], w);
        }
        // No barrier here: next stage writes g_ps[g^1] (double-buffered), and
        // its staging reads happen only after the next grid barrier.
        if (g + 1 < NSTG) __syncthreads();
    }
}

extern "C" void kernel_launch(void* const* d_in, const int* in_sizes, int n_in,
                              void* d_out, int out_size) {
    const float* x    = (const float*)d_in[0];
    const float* mu0  = (const float*)d_in[1];
    const float* var0 = (const float*)d_in[2];
    float* out = (float*)d_out;

    static bool attr_set = false;
    if (!attr_set) {
        cudaFuncSetAttribute(onorm_fused,
                             cudaFuncAttributeMaxDynamicSharedMemorySize,
                             SMEM_FLOATS * sizeof(float));
        attr_set = true;
    }

    onorm_fused<<<NCTA, TPB, SMEM_FLOATS * sizeof(float)>>>(
        (const float4*)x, (float4*)out, mu0, var0);
}